// round 11
// baseline (speedup 1.0000x reference)
#include <cuda_runtime.h>
#include <cuda_fp16.h>
#include <cstdint>

// Problem constants
#define B_ 2
#define T_ 2048
#define C_ 1024
#define H_ 16
#define D_ 64
#define BT 4096          // B_*T_
#define FF 4096          // 4*C_
#define C3 3072          // 3*C_

// ---------------- scratch (static device globals) --------------------------
__device__ __half g_h   [BT * C_];   // LN1 output (fp16)
__device__ __half g_wqkv[C3 * C_];   // QKV weights [N=3C, K=C] fp16
__device__ __half g_wp  [C_ * C_];   // Wproj^T [N,K] fp16
__device__ __half g_w1  [FF * C_];   // W1^T [N=FF, K=C] fp16
__device__ __half g_w2  [C_ * FF];   // W2^T [N=C, K=FF] fp16
__device__ __half g_qkv [BT * C3];   // fused q|k|v [B,T,3C] fp16
__device__ __half g_attn[BT * C_];   // concat heads fp16
__device__ float  g_x1  [BT * C_];   // x + attn@Wproj + bproj (fp32)
__device__ __half g_h2  [BT * C_];   // LN2 output fp16
__device__ __half g_f1  [BT * FF];   // relu(h2@W1+b1) fp16

// ---------------- helpers --------------------------------------------------
__device__ __forceinline__ void mma16(float* c, const uint32_t* a, const uint32_t* b) {
    asm volatile(
        "mma.sync.aligned.m16n8k16.row.col.f32.f16.f16.f32 "
        "{%0,%1,%2,%3}, {%4,%5,%6,%7}, {%8,%9}, {%0,%1,%2,%3};"
        : "+f"(c[0]), "+f"(c[1]), "+f"(c[2]), "+f"(c[3])
        : "r"(a[0]), "r"(a[1]), "r"(a[2]), "r"(a[3]), "r"(b[0]), "r"(b[1]));
}
#define LDSM4(R0, R1, R2, R3, addr) \
    asm volatile("ldmatrix.sync.aligned.m8n8.x4.shared.b16 {%0,%1,%2,%3}, [%4];" \
                 : "=r"(R0), "=r"(R1), "=r"(R2), "=r"(R3) : "r"(addr))
#define LDSM4T(R0, R1, R2, R3, addr) \
    asm volatile("ldmatrix.sync.aligned.m8n8.x4.trans.shared.b16 {%0,%1,%2,%3}, [%4];" \
                 : "=r"(R0), "=r"(R1), "=r"(R2), "=r"(R3) : "r"(addr))

__device__ __forceinline__ uint32_t exp2h2(float t0, float t1, float2* f) {
    __half2 hh = __floats2half2_rn(t0, t1);
    uint32_t hin = *reinterpret_cast<uint32_t*>(&hh);
    uint32_t hout;
    asm("ex2.approx.f16x2 %0, %1;" : "=r"(hout) : "r"(hin));
    __half2 he = *reinterpret_cast<__half2*>(&hout);
    *f = __half22float2(he);
    return hout;
}
__device__ __forceinline__ uint32_t smem_u32(const void* p) {
    uint32_t a;
    asm("{ .reg .u64 t; cvta.to.shared.u64 t, %1; cvt.u32.u64 %0, t; }"
        : "=r"(a) : "l"(p));
    return a;
}
#define CP16(dst, src) \
    asm volatile("cp.async.cg.shared.global [%0], [%1], 16;" \
                 :: "r"(dst), "l"(src) : "memory")
#define CP_COMMIT() asm volatile("cp.async.commit_group;" ::: "memory")
#define CP_WAIT0()  asm volatile("cp.async.wait_group 0;"  ::: "memory")
#define CP_WAIT1()  asm volatile("cp.async.wait_group 1;"  ::: "memory")

// ---------------- LayerNorm (fp32 in, fp16 out) ---------------------------
__global__ void ln_kernel(const float* __restrict__ x,
                          const float* __restrict__ sc,
                          const float* __restrict__ bi,
                          __half* __restrict__ out) {
    int row = blockIdx.x;
    const float* xr = x + (size_t)row * C_;
    __half* orow = out + (size_t)row * C_;
    int tid = threadIdx.x;

    float4 v = ((const float4*)xr)[tid];
    float s  = v.x + v.y + v.z + v.w;
    float ss = v.x*v.x + v.y*v.y + v.z*v.z + v.w*v.w;
    #pragma unroll
    for (int o = 16; o; o >>= 1) {
        s  += __shfl_xor_sync(0xffffffffu, s,  o);
        ss += __shfl_xor_sync(0xffffffffu, ss, o);
    }
    __shared__ float sm[8], sm2[8];
    if ((tid & 31) == 0) { sm[tid >> 5] = s; sm2[tid >> 5] = ss; }
    __syncthreads();
    if (tid < 32) {
        float a  = (tid < 8) ? sm[tid]  : 0.f;
        float b2 = (tid < 8) ? sm2[tid] : 0.f;
        #pragma unroll
        for (int o = 4; o; o >>= 1) {
            a  += __shfl_xor_sync(0xffffffffu, a,  o);
            b2 += __shfl_xor_sync(0xffffffffu, b2, o);
        }
        if (tid == 0) { sm[0] = a; sm2[0] = b2; }
    }
    __syncthreads();
    float mean = sm[0] * (1.f / C_);
    float var  = sm2[0] * (1.f / C_) - mean * mean;
    float rstd = rsqrtf(var + 1e-6f);

    float4 sv = ((const float4*)sc)[tid];
    float4 bv = ((const float4*)bi)[tid];
    __half2 h0 = __floats2half2_rn((v.x - mean) * rstd * sv.x + bv.x,
                                   (v.y - mean) * rstd * sv.y + bv.y);
    __half2 h1 = __floats2half2_rn((v.z - mean) * rstd * sv.z + bv.z,
                                   (v.w - mean) * rstd * sv.w + bv.w);
    uint2 o8;
    o8.x = *reinterpret_cast<uint32_t*>(&h0);
    o8.y = *reinterpret_cast<uint32_t*>(&h1);
    *(uint2*)&orow[tid * 4] = o8;
}

// ---------------- merged weight prep -------------------------------------
__global__ void prep_w(const float* __restrict__ Wq, const float* __restrict__ Wk,
                       const float* __restrict__ Wv, const float* __restrict__ Wproj,
                       const float* __restrict__ W1, const float* __restrict__ W2,
                       __half* __restrict__ wqkv, __half* __restrict__ wp,
                       __half* __restrict__ w1, __half* __restrict__ w2) {
    __shared__ float t[32][33];
    int tIdx = blockIdx.x;
    const float* src; __half* dst;
    int R, Cc, bx, by;
    if (tIdx < 3072) {
        int w = tIdx >> 10, rem = tIdx & 1023;
        int head = rem >> 6, q = rem & 63;
        bx = q & 1; by = q >> 1;
        const float* Wsrc = (w == 0) ? Wq : (w == 1) ? Wk : Wv;
        src = Wsrc + (size_t)head * C_ * 64;
        dst = wqkv + (size_t)w * C_ * C_ + (size_t)head * 64 * C_;
        R = C_; Cc = 64;
    } else if (tIdx < 4096) {
        int rem = tIdx - 3072;
        bx = rem & 31; by = rem >> 5;
        src = Wproj; dst = wp; R = C_; Cc = C_;
    } else if (tIdx < 8192) {
        int rem = tIdx - 4096;
        bx = rem & 127; by = rem >> 7;
        src = W1; dst = w1; R = C_; Cc = FF;
    } else {
        int rem = tIdx - 8192;
        bx = rem & 31; by = rem >> 5;
        src = W2; dst = w2; R = FF; Cc = C_;
    }
    int r0 = by * 32, c0 = bx * 32;
    int x = threadIdx.x, y = threadIdx.y;
    #pragma unroll
    for (int i = 0; i < 32; i += 8)
        t[y + i][x] = src[(size_t)(r0 + y + i) * Cc + c0 + x];
    __syncthreads();
    #pragma unroll
    for (int i = 0; i < 32; i += 8)
        dst[(size_t)(c0 + y + i) * R + r0 + x] = __float2half(t[x][y + i]);
}

// ---------------- fp16 GEMM (BK=64, 3-stage cp.async, ldmatrix) ------------
#define H_SA 72                       // halves stride (144 B)
#define H_STG_H (128 * H_SA * 2)      // A+B halves per stage
#define H_BOFF  (128 * H_SA)
#define H_STG_BY (H_STG_H * 2)        // 36864 bytes
#define H_SMEM  (3 * H_STG_BY)        // 110592 bytes

template <int RELU, int HOUT>
__global__ void __launch_bounds__(256, 2) hgemm(
    const __half* __restrict__ A, const __half* __restrict__ Bw,
    const float* __restrict__ bias, const float* __restrict__ resid,
    void* __restrict__ Cout, int M, int N, int K)
{
    extern __shared__ __half smh[];
    uint32_t sbase = smem_u32(smh);

    int tid  = threadIdx.x;
    int wid  = tid >> 5, lane = tid & 31;
    int g    = lane >> 2, r = lane & 3;
    int bm   = blockIdx.y, bn = blockIdx.x;
    int wm   = (wid & 1) * 64;
    int wn   = (wid >> 1) * 32;

    const __half* Ab = A  + (size_t)bm * 128 * K;
    const __half* Bb = Bw + (size_t)bn * 128 * K;

    int lr = tid >> 3, seg = tid & 7;
    const __half* Asrc = Ab + (size_t)lr * K + seg * 8;
    const __half* Bsrc = Bb + (size_t)lr * K + seg * 8;
    uint32_t ad = sbase + (uint32_t)(lr * 144 + seg * 16);
    uint32_t bd = ad + H_BOFF * 2;
    const size_t r32 = (size_t)32 * K;

    uint32_t aoff = (uint32_t)(((lane & 7) + ((lane >> 3) & 1) * 8) * H_SA
                               + (lane >> 4) * 8) * 2;
    uint32_t boff = (uint32_t)(((lane & 7) + ((lane >> 4) & 1) * 8) * H_SA
                               + ((lane >> 3) & 1) * 8) * 2;

    float c[4][4][4];
    #pragma unroll
    for (int mt = 0; mt < 4; mt++)
        #pragma unroll
        for (int nt = 0; nt < 4; nt++)
            #pragma unroll
            for (int i = 0; i < 4; i++) c[mt][nt][i] = 0.f;

    int nch = K >> 6;

    // prologue: 2 stages in flight
    #pragma unroll
    for (int pc = 0; pc < 2; pc++) {
        uint32_t so = (uint32_t)pc * H_STG_BY;
        int kt = pc << 6;
        #pragma unroll
        for (int p = 0; p < 4; p++) {
            CP16(ad + so + (uint32_t)p * 32 * 144, Asrc + p * r32 + kt);
            CP16(bd + so + (uint32_t)p * 32 * 144, Bsrc + p * r32 + kt);
        }
        CP_COMMIT();
    }

    for (int ch = 0; ch < nch; ch++) {
        int st = ch % 3;
        CP_WAIT1();
        __syncthreads();

        // issue next prefetch FIRST so it overlaps the whole compute chunk
        int nc2 = ch + 2;
        if (nc2 < nch) {
            int kt = nc2 << 6;
            uint32_t so = (uint32_t)(nc2 % 3) * H_STG_BY;
            #pragma unroll
            for (int p = 0; p < 4; p++) {
                CP16(ad + so + (uint32_t)p * 32 * 144, Asrc + p * r32 + kt);
                CP16(bd + so + (uint32_t)p * 32 * 144, Bsrc + p * r32 + kt);
            }
        }
        CP_COMMIT();

        uint32_t abase = sbase + (uint32_t)st * H_STG_BY + aoff;
        uint32_t bbase = sbase + (uint32_t)st * H_STG_BY + H_BOFF * 2 + boff;
        #pragma unroll
        for (int ks = 0; ks < 4; ks++) {
            int kk = ks * 16;
            uint32_t af[4][4], bf[4][2];
            #pragma unroll
            for (int mt = 0; mt < 4; mt++)
                LDSM4(af[mt][0], af[mt][1], af[mt][2], af[mt][3],
                      abase + (uint32_t)(((wm + mt * 16) * H_SA + kk) * 2));
            #pragma unroll
            for (int np = 0; np < 2; np++) {
                uint32_t r0, r1, r2, r3;
                LDSM4(r0, r1, r2, r3,
                      bbase + (uint32_t)(((wn + np * 16) * H_SA + kk) * 2));
                bf[2 * np][0] = r0; bf[2 * np][1] = r1;
                bf[2 * np + 1][0] = r2; bf[2 * np + 1][1] = r3;
            }
            #pragma unroll
            for (int mt = 0; mt < 4; mt++)
                #pragma unroll
                for (int nt = 0; nt < 4; nt++)
                    mma16(c[mt][nt], af[mt], bf[nt]);
        }
    }

    #pragma unroll
    for (int mt = 0; mt < 4; mt++) {
        #pragma unroll
        for (int rr = 0; rr < 2; rr++) {
            int m = bm * 128 + wm + mt * 16 + g + rr * 8;
            const float* Rrow = resid ? resid + (size_t)m * N + bn * 128 : nullptr;
            #pragma unroll
            for (int nt = 0; nt < 4; nt++) {
                int nc = wn + nt * 8 + 2 * r;
                float v0 = c[mt][nt][rr * 2 + 0];
                float v1 = c[mt][nt][rr * 2 + 1];
                if (bias)  { v0 += bias[bn * 128 + nc]; v1 += bias[bn * 128 + nc + 1]; }
                if (resid) { v0 += Rrow[nc]; v1 += Rrow[nc + 1]; }
                if (RELU)  { v0 = fmaxf(v0, 0.f); v1 = fmaxf(v1, 0.f); }
                if (HOUT) {
                    __half* Crow = (__half*)Cout + (size_t)m * N + bn * 128;
                    *(__half2*)&Crow[nc] = __floats2half2_rn(v0, v1);
                } else {
                    float* Crow = (float*)Cout + (size_t)m * N + bn * 128;
                    *(float2*)&Crow[nc] = make_float2(v0, v1);
                }
            }
        }
    }
}

// ---------------- fp16 flash attention: cp.async K/V + register P ----------
#define AT_S 72
#define AT_STG_H (2 * 64 * AT_S)                 // K+V halves per stage = 9216
#define AT_STG_BY (AT_STG_H * 2)                 // 18432 bytes
#define ATT_SMEM_BYTES (2 * AT_STG_BY)           // 36864 bytes (2 stages)
#define LOG2E 1.4426950408889634f

__global__ void __launch_bounds__(256, 2) attn_h(
    const __half* __restrict__ QKV, __half* __restrict__ O)
{
    extern __shared__ __half sma[];
    uint32_t sbase = smem_u32(sma);

    int tid = threadIdx.x;
    int wid = tid >> 5, lane = tid & 31;
    int g = lane >> 2, r = lane & 3;
    int b = blockIdx.y >> 4, h = blockIdx.y & 15;
    // reversed order: heaviest (largest q0) CTAs launch first
    int q0 = (gridDim.x - 1 - blockIdx.x) * 128;
    int m0 = wid * 16;

    const __half* Qb = QKV + (size_t)b * T_ * C3 + h * 64;
    const __half* Kb = Qb + C_;
    const __half* Vb = Qb + 2 * C_;

    int row0 = q0 + m0 + g;
    int row1 = row0 + 8;

    uint32_t kb_off = (uint32_t)(((lane & 7) + ((lane >> 4) & 1) * 8) * AT_S
                                 + ((lane >> 3) & 1) * 8) * 2;
    uint32_t vb_off = (uint32_t)(((lane & 7) + ((lane >> 3) & 1) * 8) * AT_S
                                 + (lane >> 4) * 8) * 2;

    // cp.async src/dst mapping: row lr & lr+32, 16B segment seg
    int lr = tid >> 3, seg = tid & 7;
    const __half* Ksrc = Kb + (size_t)lr * C3 + seg * 8;
    const __half* Vsrc = Vb + (size_t)lr * C3 + seg * 8;
    uint32_t kd = sbase + (uint32_t)(lr * AT_S + seg * 8) * 2;
    uint32_t vd = kd + 64 * AT_S * 2;
    const size_t r32g = (size_t)32 * C3;

    uint32_t qa[4][4];
    #pragma unroll
    for (int kc = 0; kc < 4; kc++) {
        int d0 = kc * 16;
        qa[kc][0] = *(const uint32_t*)&Qb[(size_t)row0 * C3 + d0 + 2 * r    ];
        qa[kc][1] = *(const uint32_t*)&Qb[(size_t)row1 * C3 + d0 + 2 * r    ];
        qa[kc][2] = *(const uint32_t*)&Qb[(size_t)row0 * C3 + d0 + 2 * r + 8];
        qa[kc][3] = *(const uint32_t*)&Qb[(size_t)row1 * C3 + d0 + 2 * r + 8];
    }

    float oa[8][4];
    #pragma unroll
    for (int nt = 0; nt < 8; nt++)
        #pragma unroll
        for (int i = 0; i < 4; i++) oa[nt][i] = 0.f;
    float mi0 = -1e30f, mi1 = -1e30f, li0 = 0.f, li1 = 0.f;

    int ntiles = (q0 >> 6) + 2;

    // prologue: load tile 0 into stage 0
    {
        CP16(kd, Ksrc);                      CP16(kd + 32 * AT_S * 2, Ksrc + r32g);
        CP16(vd, Vsrc);                      CP16(vd + 32 * AT_S * 2, Vsrc + r32g);
        CP_COMMIT();
    }

    for (int kt = 0; kt < ntiles; kt++) {
        CP_WAIT0();
        __syncthreads();

        // prefetch next tile into the other stage (overlaps compute below)
        if (kt + 1 < ntiles) {
            int kn = (kt + 1) << 6;
            uint32_t so = (uint32_t)((kt + 1) & 1) * AT_STG_BY;
            const __half* Ks2 = Ksrc + (size_t)kn * C3;
            const __half* Vs2 = Vsrc + (size_t)kn * C3;
            CP16(kd + so, Ks2);              CP16(kd + so + 32 * AT_S * 2, Ks2 + r32g);
            CP16(vd + so, Vs2);              CP16(vd + so + 32 * AT_S * 2, Vs2 + r32g);
            CP_COMMIT();
        }

        int k0 = kt << 6;
        uint32_t stg = sbase + (uint32_t)(kt & 1) * AT_STG_BY;
        uint32_t ks_b = stg;
        uint32_t vs_b = stg + 64 * AT_S * 2;

        // ---- S = Q K^T ----
        float sc[8][4];
        #pragma unroll
        for (int nt = 0; nt < 8; nt++)
            #pragma unroll
            for (int i = 0; i < 4; i++) sc[nt][i] = 0.f;
        #pragma unroll
        for (int kc = 0; kc < 4; kc++) {
            int kk = kc * 16;
            #pragma unroll
            for (int np = 0; np < 4; np++) {
                uint32_t r0, r1, r2, r3;
                LDSM4(r0, r1, r2, r3,
                      ks_b + kb_off + (uint32_t)((np * 16 * AT_S + kk) * 2));
                uint32_t b0[2] = {r0, r1}, b1[2] = {r2, r3};
                mma16(sc[2 * np],     qa[kc], b0);
                mma16(sc[2 * np + 1], qa[kc], b1);
            }
        }

        // ---- scale + causal mask + row max ----
        float mx0 = -1e30f, mx1 = -1e30f;
        #pragma unroll
        for (int nt = 0; nt < 8; nt++) {
            int c0 = k0 + nt * 8 + 2 * r;
            int c1 = c0 + 1;
            sc[nt][0] = (c0 <= row0) ? sc[nt][0] * 0.03125f : -1e30f;
            sc[nt][1] = (c1 <= row0) ? sc[nt][1] * 0.03125f : -1e30f;
            sc[nt][2] = (c0 <= row1) ? sc[nt][2] * 0.03125f : -1e30f;
            sc[nt][3] = (c1 <= row1) ? sc[nt][3] * 0.03125f : -1e30f;
            mx0 = fmaxf(mx0, fmaxf(sc[nt][0], sc[nt][1]));
            mx1 = fmaxf(mx1, fmaxf(sc[nt][2], sc[nt][3]));
        }
        mx0 = fmaxf(mx0, __shfl_xor_sync(0xffffffffu, mx0, 1));
        mx0 = fmaxf(mx0, __shfl_xor_sync(0xffffffffu, mx0, 2));
        mx1 = fmaxf(mx1, __shfl_xor_sync(0xffffffffu, mx1, 1));
        mx1 = fmaxf(mx1, __shfl_xor_sync(0xffffffffu, mx1, 2));

        float mn0 = fmaxf(mi0, mx0), mn1 = fmaxf(mi1, mx1);
        float corr0 = __expf(mi0 - mn0);
        float corr1 = __expf(mi1 - mn1);

        // ---- exp; P packed in registers ----
        uint32_t hp0[8], hp1[8];
        float s0 = 0.f, s1 = 0.f;
        #pragma unroll
        for (int nt = 0; nt < 8; nt++) {
            float2 f01, f23;
            hp0[nt] = exp2h2((sc[nt][0] - mn0) * LOG2E,
                             (sc[nt][1] - mn0) * LOG2E, &f01);
            hp1[nt] = exp2h2((sc[nt][2] - mn1) * LOG2E,
                             (sc[nt][3] - mn1) * LOG2E, &f23);
            s0 += f01.x + f01.y;
            s1 += f23.x + f23.y;
        }
        s0 += __shfl_xor_sync(0xffffffffu, s0, 1);
        s0 += __shfl_xor_sync(0xffffffffu, s0, 2);
        s1 += __shfl_xor_sync(0xffffffffu, s1, 1);
        s1 += __shfl_xor_sync(0xffffffffu, s1, 2);
        li0 = li0 * corr0 + s0;
        li1 = li1 * corr1 + s1;
        mi0 = mn0; mi1 = mn1;

        #pragma unroll
        for (int nt = 0; nt < 8; nt++) {
            oa[nt][0] *= corr0; oa[nt][1] *= corr0;
            oa[nt][2] *= corr1; oa[nt][3] *= corr1;
        }

        // ---- O += P V ----
        #pragma unroll
        for (int scx = 0; scx < 4; scx++) {
            int s8 = scx * 16;
            uint32_t pa[4] = {hp0[2 * scx], hp1[2 * scx],
                              hp0[2 * scx + 1], hp1[2 * scx + 1]};
            #pragma unroll
            for (int np = 0; np < 4; np++) {
                uint32_t r0, r1, r2, r3;
                LDSM4T(r0, r1, r2, r3,
                       vs_b + vb_off + (uint32_t)((s8 * AT_S + np * 16) * 2));
                uint32_t b0[2] = {r0, r1}, b1[2] = {r2, r3};
                mma16(oa[2 * np],     pa, b0);
                mma16(oa[2 * np + 1], pa, b1);
            }
        }
    }

    float inv0 = 1.f / li0, inv1 = 1.f / li1;
    __half* Ob = O + (size_t)b * T_ * C_ + h * 64;
    #pragma unroll
    for (int nt = 0; nt < 8; nt++) {
        int cc = nt * 8 + 2 * r;
        *(__half2*)&Ob[(size_t)row0 * C_ + cc] =
            __floats2half2_rn(oa[nt][0] * inv0, oa[nt][1] * inv0);
        *(__half2*)&Ob[(size_t)row1 * C_ + cc] =
            __floats2half2_rn(oa[nt][2] * inv1, oa[nt][3] * inv1);
    }
}

// ---------------- launcher -------------------------------------------------
extern "C" void kernel_launch(void* const* d_in, const int* in_sizes, int n_in,
                              void* d_out, int out_size) {
    const float* x     = (const float*)d_in[0];
    const float* Wq    = (const float*)d_in[1];
    const float* Wk    = (const float*)d_in[2];
    const float* Wv    = (const float*)d_in[3];
    const float* Wproj = (const float*)d_in[4];
    const float* bproj = (const float*)d_in[5];
    const float* W1    = (const float*)d_in[6];
    const float* b1    = (const float*)d_in[7];
    const float* W2    = (const float*)d_in[8];
    const float* b2    = (const float*)d_in[9];
    const float* ln1s  = (const float*)d_in[10];
    const float* ln1b  = (const float*)d_in[11];
    const float* ln2s  = (const float*)d_in[12];
    const float* ln2b  = (const float*)d_in[13];
    float* out = (float*)d_out;

    __half *h, *wqkv, *wp, *w1, *w2, *qkv, *attn, *h2, *f1;
    float *x1;
    cudaGetSymbolAddress((void**)&h,    g_h);
    cudaGetSymbolAddress((void**)&wqkv, g_wqkv);
    cudaGetSymbolAddress((void**)&wp,   g_wp);
    cudaGetSymbolAddress((void**)&w1,   g_w1);
    cudaGetSymbolAddress((void**)&w2,   g_w2);
    cudaGetSymbolAddress((void**)&qkv,  g_qkv);
    cudaGetSymbolAddress((void**)&attn, g_attn);
    cudaGetSymbolAddress((void**)&x1,   g_x1);
    cudaGetSymbolAddress((void**)&h2,   g_h2);
    cudaGetSymbolAddress((void**)&f1,   g_f1);

    cudaFuncSetAttribute(attn_h,
                         cudaFuncAttributeMaxDynamicSharedMemorySize, ATT_SMEM_BYTES);
    cudaFuncSetAttribute(hgemm<0, 0>,
                         cudaFuncAttributeMaxDynamicSharedMemorySize, H_SMEM);
    cudaFuncSetAttribute(hgemm<0, 1>,
                         cudaFuncAttributeMaxDynamicSharedMemorySize, H_SMEM);
    cudaFuncSetAttribute(hgemm<1, 1>,
                         cudaFuncAttributeMaxDynamicSharedMemorySize, H_SMEM);

    // LN1 + merged weight prep
    ln_kernel<<<BT, 256>>>(x, ln1s, ln1b, h);
    prep_w<<<12288, dim3(32, 8)>>>(Wq, Wk, Wv, Wproj, W1, W2, wqkv, wp, w1, w2);

    // fused QKV projection (fp16 out)
    hgemm<0, 1><<<dim3(C3 / 128, BT / 128), 256, H_SMEM>>>(
        h, wqkv, nullptr, nullptr, qkv, BT, C3, C_);

    // attention
    attn_h<<<dim3(T_ / 128, B_ * H_), 256, ATT_SMEM_BYTES>>>(qkv, attn);

    // out proj + residual (fp32 out)
    dim3 g1(C_ / 128, BT / 128);
    hgemm<0, 0><<<g1, 256, H_SMEM>>>(attn, wp, bproj, x, x1, BT, C_, C_);

    // LN2 (fp16 out)
    ln_kernel<<<BT, 256>>>(x1, ln2s, ln2b, h2);

    // MLP
    hgemm<1, 1><<<dim3(FF / 128, BT / 128), 256, H_SMEM>>>(
        h2, w1, b1, nullptr, f1, BT, FF, C_);
    hgemm<0, 0><<<g1, 256, H_SMEM>>>(f1, w2, b2, x1, out, BT, C_, FF);
}

// round 12
// speedup vs baseline: 1.0596x; 1.0596x over previous
#include <cuda_runtime.h>
#include <cuda_fp16.h>
#include <cstdint>

// Problem constants
#define B_ 2
#define T_ 2048
#define C_ 1024
#define H_ 16
#define D_ 64
#define BT 4096          // B_*T_
#define FF 4096          // 4*C_
#define C3 3072          // 3*C_

// ---------------- scratch (static device globals) --------------------------
__device__ __half g_h   [BT * C_];   // LN1 output (fp16)
__device__ __half g_wqkv[C3 * C_];   // QKV weights [N=3C, K=C] fp16
__device__ __half g_wp  [C_ * C_];   // Wproj^T [N,K] fp16
__device__ __half g_w1  [FF * C_];   // W1^T [N=FF, K=C] fp16
__device__ __half g_w2  [C_ * FF];   // W2^T [N=C, K=FF] fp16
__device__ __half g_qkv [BT * C3];   // fused q|k|v [B,T,3C] fp16
__device__ __half g_attn[BT * C_];   // concat heads fp16
__device__ float  g_x1  [BT * C_];   // x + attn@Wproj + bproj (fp32)
__device__ __half g_h2  [BT * C_];   // LN2 output fp16
__device__ __half g_f1  [BT * FF];   // relu(h2@W1+b1) fp16

// ---------------- helpers --------------------------------------------------
__device__ __forceinline__ void mma16(float* c, const uint32_t* a, const uint32_t* b) {
    asm volatile(
        "mma.sync.aligned.m16n8k16.row.col.f32.f16.f16.f32 "
        "{%0,%1,%2,%3}, {%4,%5,%6,%7}, {%8,%9}, {%0,%1,%2,%3};"
        : "+f"(c[0]), "+f"(c[1]), "+f"(c[2]), "+f"(c[3])
        : "r"(a[0]), "r"(a[1]), "r"(a[2]), "r"(a[3]), "r"(b[0]), "r"(b[1]));
}
#define LDSM4(R0, R1, R2, R3, addr) \
    asm volatile("ldmatrix.sync.aligned.m8n8.x4.shared.b16 {%0,%1,%2,%3}, [%4];" \
                 : "=r"(R0), "=r"(R1), "=r"(R2), "=r"(R3) : "r"(addr))
#define LDSM4T(R0, R1, R2, R3, addr) \
    asm volatile("ldmatrix.sync.aligned.m8n8.x4.trans.shared.b16 {%0,%1,%2,%3}, [%4];" \
                 : "=r"(R0), "=r"(R1), "=r"(R2), "=r"(R3) : "r"(addr))

__device__ __forceinline__ uint32_t exp2h2(float t0, float t1, float2* f) {
    __half2 hh = __floats2half2_rn(t0, t1);
    uint32_t hin = *reinterpret_cast<uint32_t*>(&hh);
    uint32_t hout;
    asm("ex2.approx.f16x2 %0, %1;" : "=r"(hout) : "r"(hin));
    __half2 he = *reinterpret_cast<__half2*>(&hout);
    *f = __half22float2(he);
    return hout;
}
__device__ __forceinline__ uint32_t smem_u32(const void* p) {
    uint32_t a;
    asm("{ .reg .u64 t; cvta.to.shared.u64 t, %1; cvt.u32.u64 %0, t; }"
        : "=r"(a) : "l"(p));
    return a;
}
#define CP16(dst, src) \
    asm volatile("cp.async.cg.shared.global [%0], [%1], 16;" \
                 :: "r"(dst), "l"(src) : "memory")
#define CP_COMMIT() asm volatile("cp.async.commit_group;" ::: "memory")
#define CP_WAIT0()  asm volatile("cp.async.wait_group 0;"  ::: "memory")
#define CP_WAIT1()  asm volatile("cp.async.wait_group 1;"  ::: "memory")

// ---------------- LayerNorm (fp32 in, fp16 out) ---------------------------
__global__ void ln_kernel(const float* __restrict__ x,
                          const float* __restrict__ sc,
                          const float* __restrict__ bi,
                          __half* __restrict__ out) {
    int row = blockIdx.x;
    const float* xr = x + (size_t)row * C_;
    __half* orow = out + (size_t)row * C_;
    int tid = threadIdx.x;

    float4 v = ((const float4*)xr)[tid];
    float s  = v.x + v.y + v.z + v.w;
    float ss = v.x*v.x + v.y*v.y + v.z*v.z + v.w*v.w;
    #pragma unroll
    for (int o = 16; o; o >>= 1) {
        s  += __shfl_xor_sync(0xffffffffu, s,  o);
        ss += __shfl_xor_sync(0xffffffffu, ss, o);
    }
    __shared__ float sm[8], sm2[8];
    if ((tid & 31) == 0) { sm[tid >> 5] = s; sm2[tid >> 5] = ss; }
    __syncthreads();
    if (tid < 32) {
        float a  = (tid < 8) ? sm[tid]  : 0.f;
        float b2 = (tid < 8) ? sm2[tid] : 0.f;
        #pragma unroll
        for (int o = 4; o; o >>= 1) {
            a  += __shfl_xor_sync(0xffffffffu, a,  o);
            b2 += __shfl_xor_sync(0xffffffffu, b2, o);
        }
        if (tid == 0) { sm[0] = a; sm2[0] = b2; }
    }
    __syncthreads();
    float mean = sm[0] * (1.f / C_);
    float var  = sm2[0] * (1.f / C_) - mean * mean;
    float rstd = rsqrtf(var + 1e-6f);

    float4 sv = ((const float4*)sc)[tid];
    float4 bv = ((const float4*)bi)[tid];
    __half2 h0 = __floats2half2_rn((v.x - mean) * rstd * sv.x + bv.x,
                                   (v.y - mean) * rstd * sv.y + bv.y);
    __half2 h1 = __floats2half2_rn((v.z - mean) * rstd * sv.z + bv.z,
                                   (v.w - mean) * rstd * sv.w + bv.w);
    uint2 o8;
    o8.x = *reinterpret_cast<uint32_t*>(&h0);
    o8.y = *reinterpret_cast<uint32_t*>(&h1);
    *(uint2*)&orow[tid * 4] = o8;
}

// ---------------- merged weight prep -------------------------------------
__global__ void prep_w(const float* __restrict__ Wq, const float* __restrict__ Wk,
                       const float* __restrict__ Wv, const float* __restrict__ Wproj,
                       const float* __restrict__ W1, const float* __restrict__ W2,
                       __half* __restrict__ wqkv, __half* __restrict__ wp,
                       __half* __restrict__ w1, __half* __restrict__ w2) {
    __shared__ float t[32][33];
    int tIdx = blockIdx.x;
    const float* src; __half* dst;
    int R, Cc, bx, by;
    if (tIdx < 3072) {
        int w = tIdx >> 10, rem = tIdx & 1023;
        int head = rem >> 6, q = rem & 63;
        bx = q & 1; by = q >> 1;
        const float* Wsrc = (w == 0) ? Wq : (w == 1) ? Wk : Wv;
        src = Wsrc + (size_t)head * C_ * 64;
        dst = wqkv + (size_t)w * C_ * C_ + (size_t)head * 64 * C_;
        R = C_; Cc = 64;
    } else if (tIdx < 4096) {
        int rem = tIdx - 3072;
        bx = rem & 31; by = rem >> 5;
        src = Wproj; dst = wp; R = C_; Cc = C_;
    } else if (tIdx < 8192) {
        int rem = tIdx - 4096;
        bx = rem & 127; by = rem >> 7;
        src = W1; dst = w1; R = C_; Cc = FF;
    } else {
        int rem = tIdx - 8192;
        bx = rem & 31; by = rem >> 5;
        src = W2; dst = w2; R = FF; Cc = C_;
    }
    int r0 = by * 32, c0 = bx * 32;
    int x = threadIdx.x, y = threadIdx.y;
    #pragma unroll
    for (int i = 0; i < 32; i += 8)
        t[y + i][x] = src[(size_t)(r0 + y + i) * Cc + c0 + x];
    __syncthreads();
    #pragma unroll
    for (int i = 0; i < 32; i += 8)
        dst[(size_t)(c0 + y + i) * R + r0 + x] = __float2half(t[x][y + i]);
}

// ---------------- fp16 GEMM (BK=64, 3-stage cp.async, ldmatrix) ------------
// R10-validated ordering: compute first, prefetch after, commit at loop end.
#define H_SA 72                       // halves stride (144 B)
#define H_STG_H (128 * H_SA * 2)      // A+B halves per stage
#define H_BOFF  (128 * H_SA)
#define H_STG_BY (H_STG_H * 2)        // 36864 bytes
#define H_SMEM  (3 * H_STG_BY)        // 110592 bytes

template <int RELU, int HOUT>
__global__ void __launch_bounds__(256, 2) hgemm(
    const __half* __restrict__ A, const __half* __restrict__ Bw,
    const float* __restrict__ bias, const float* __restrict__ resid,
    void* __restrict__ Cout, int M, int N, int K)
{
    extern __shared__ __half smh[];
    uint32_t sbase = smem_u32(smh);

    int tid  = threadIdx.x;
    int wid  = tid >> 5, lane = tid & 31;
    int g    = lane >> 2, r = lane & 3;
    int bm   = blockIdx.y, bn = blockIdx.x;
    int wm   = (wid & 1) * 64;
    int wn   = (wid >> 1) * 32;

    const __half* Ab = A  + (size_t)bm * 128 * K;
    const __half* Bb = Bw + (size_t)bn * 128 * K;

    int lr = tid >> 3, seg = tid & 7;
    const __half* Asrc = Ab + (size_t)lr * K + seg * 8;
    const __half* Bsrc = Bb + (size_t)lr * K + seg * 8;
    uint32_t ad = sbase + (uint32_t)(lr * 144 + seg * 16);
    uint32_t bd = ad + H_BOFF * 2;
    const size_t r32 = (size_t)32 * K;

    uint32_t aoff = (uint32_t)(((lane & 7) + ((lane >> 3) & 1) * 8) * H_SA
                               + (lane >> 4) * 8) * 2;
    uint32_t boff = (uint32_t)(((lane & 7) + ((lane >> 4) & 1) * 8) * H_SA
                               + ((lane >> 3) & 1) * 8) * 2;

    float c[4][4][4];
    #pragma unroll
    for (int mt = 0; mt < 4; mt++)
        #pragma unroll
        for (int nt = 0; nt < 4; nt++)
            #pragma unroll
            for (int i = 0; i < 4; i++) c[mt][nt][i] = 0.f;

    int nch = K >> 6;

    // prologue: 2 stages in flight
    #pragma unroll
    for (int pc = 0; pc < 2; pc++) {
        uint32_t so = (uint32_t)pc * H_STG_BY;
        int kt = pc << 6;
        #pragma unroll
        for (int p = 0; p < 4; p++) {
            CP16(ad + so + (uint32_t)p * 32 * 144, Asrc + p * r32 + kt);
            CP16(bd + so + (uint32_t)p * 32 * 144, Bsrc + p * r32 + kt);
        }
        CP_COMMIT();
    }

    for (int ch = 0; ch < nch; ch++) {
        int st = ch % 3;
        CP_WAIT1();
        __syncthreads();

        uint32_t abase = sbase + (uint32_t)st * H_STG_BY + aoff;
        uint32_t bbase = sbase + (uint32_t)st * H_STG_BY + H_BOFF * 2 + boff;
        #pragma unroll
        for (int ks = 0; ks < 4; ks++) {
            int kk = ks * 16;
            uint32_t af[4][4], bf[4][2];
            #pragma unroll
            for (int mt = 0; mt < 4; mt++)
                LDSM4(af[mt][0], af[mt][1], af[mt][2], af[mt][3],
                      abase + (uint32_t)(((wm + mt * 16) * H_SA + kk) * 2));
            #pragma unroll
            for (int np = 0; np < 2; np++) {
                uint32_t r0, r1, r2, r3;
                LDSM4(r0, r1, r2, r3,
                      bbase + (uint32_t)(((wn + np * 16) * H_SA + kk) * 2));
                bf[2 * np][0] = r0; bf[2 * np][1] = r1;
                bf[2 * np + 1][0] = r2; bf[2 * np + 1][1] = r3;
            }
            #pragma unroll
            for (int mt = 0; mt < 4; mt++)
                #pragma unroll
                for (int nt = 0; nt < 4; nt++)
                    mma16(c[mt][nt], af[mt], bf[nt]);
        }

        int nc2 = ch + 2;
        if (nc2 < nch) {
            int kt = nc2 << 6;
            uint32_t so = (uint32_t)(nc2 % 3) * H_STG_BY;
            #pragma unroll
            for (int p = 0; p < 4; p++) {
                CP16(ad + so + (uint32_t)p * 32 * 144, Asrc + p * r32 + kt);
                CP16(bd + so + (uint32_t)p * 32 * 144, Bsrc + p * r32 + kt);
            }
        }
        CP_COMMIT();
    }

    #pragma unroll
    for (int mt = 0; mt < 4; mt++) {
        #pragma unroll
        for (int rr = 0; rr < 2; rr++) {
            int m = bm * 128 + wm + mt * 16 + g + rr * 8;
            const float* Rrow = resid ? resid + (size_t)m * N + bn * 128 : nullptr;
            #pragma unroll
            for (int nt = 0; nt < 4; nt++) {
                int nc = wn + nt * 8 + 2 * r;
                float v0 = c[mt][nt][rr * 2 + 0];
                float v1 = c[mt][nt][rr * 2 + 1];
                if (bias)  { v0 += bias[bn * 128 + nc]; v1 += bias[bn * 128 + nc + 1]; }
                if (resid) { v0 += Rrow[nc]; v1 += Rrow[nc + 1]; }
                if (RELU)  { v0 = fmaxf(v0, 0.f); v1 = fmaxf(v1, 0.f); }
                if (HOUT) {
                    __half* Crow = (__half*)Cout + (size_t)m * N + bn * 128;
                    *(__half2*)&Crow[nc] = __floats2half2_rn(v0, v1);
                } else {
                    float* Crow = (float*)Cout + (size_t)m * N + bn * 128;
                    *(float2*)&Crow[nc] = make_float2(v0, v1);
                }
            }
        }
    }
}

// ---------------- fp16 flash attention: cp.async K/V + register P ----------
// (R11-validated: 112.4us, L1 34%, reversed causal CTA order)
#define AT_S 72
#define AT_STG_H (2 * 64 * AT_S)                 // K+V halves per stage
#define AT_STG_BY (AT_STG_H * 2)                 // 18432 bytes
#define ATT_SMEM_BYTES (2 * AT_STG_BY)           // 36864 bytes (2 stages)
#define LOG2E 1.4426950408889634f

__global__ void __launch_bounds__(256, 2) attn_h(
    const __half* __restrict__ QKV, __half* __restrict__ O)
{
    extern __shared__ __half sma[];
    uint32_t sbase = smem_u32(sma);

    int tid = threadIdx.x;
    int wid = tid >> 5, lane = tid & 31;
    int g = lane >> 2, r = lane & 3;
    int b = blockIdx.y >> 4, h = blockIdx.y & 15;
    // reversed order: heaviest (largest q0) CTAs launch first
    int q0 = (gridDim.x - 1 - blockIdx.x) * 128;
    int m0 = wid * 16;

    const __half* Qb = QKV + (size_t)b * T_ * C3 + h * 64;
    const __half* Kb = Qb + C_;
    const __half* Vb = Qb + 2 * C_;

    int row0 = q0 + m0 + g;
    int row1 = row0 + 8;

    uint32_t kb_off = (uint32_t)(((lane & 7) + ((lane >> 4) & 1) * 8) * AT_S
                                 + ((lane >> 3) & 1) * 8) * 2;
    uint32_t vb_off = (uint32_t)(((lane & 7) + ((lane >> 3) & 1) * 8) * AT_S
                                 + (lane >> 4) * 8) * 2;

    int lr = tid >> 3, seg = tid & 7;
    const __half* Ksrc = Kb + (size_t)lr * C3 + seg * 8;
    const __half* Vsrc = Vb + (size_t)lr * C3 + seg * 8;
    uint32_t kd = sbase + (uint32_t)(lr * AT_S + seg * 8) * 2;
    uint32_t vd = kd + 64 * AT_S * 2;
    const size_t r32g = (size_t)32 * C3;

    uint32_t qa[4][4];
    #pragma unroll
    for (int kc = 0; kc < 4; kc++) {
        int d0 = kc * 16;
        qa[kc][0] = *(const uint32_t*)&Qb[(size_t)row0 * C3 + d0 + 2 * r    ];
        qa[kc][1] = *(const uint32_t*)&Qb[(size_t)row1 * C3 + d0 + 2 * r    ];
        qa[kc][2] = *(const uint32_t*)&Qb[(size_t)row0 * C3 + d0 + 2 * r + 8];
        qa[kc][3] = *(const uint32_t*)&Qb[(size_t)row1 * C3 + d0 + 2 * r + 8];
    }

    float oa[8][4];
    #pragma unroll
    for (int nt = 0; nt < 8; nt++)
        #pragma unroll
        for (int i = 0; i < 4; i++) oa[nt][i] = 0.f;
    float mi0 = -1e30f, mi1 = -1e30f, li0 = 0.f, li1 = 0.f;

    int ntiles = (q0 >> 6) + 2;

    // prologue: load tile 0 into stage 0
    {
        CP16(kd, Ksrc);                      CP16(kd + 32 * AT_S * 2, Ksrc + r32g);
        CP16(vd, Vsrc);                      CP16(vd + 32 * AT_S * 2, Vsrc + r32g);
        CP_COMMIT();
    }

    for (int kt = 0; kt < ntiles; kt++) {
        CP_WAIT0();
        __syncthreads();

        // prefetch next tile into the other stage (overlaps compute below)
        if (kt + 1 < ntiles) {
            int kn = (kt + 1) << 6;
            uint32_t so = (uint32_t)((kt + 1) & 1) * AT_STG_BY;
            const __half* Ks2 = Ksrc + (size_t)kn * C3;
            const __half* Vs2 = Vsrc + (size_t)kn * C3;
            CP16(kd + so, Ks2);              CP16(kd + so + 32 * AT_S * 2, Ks2 + r32g);
            CP16(vd + so, Vs2);              CP16(vd + so + 32 * AT_S * 2, Vs2 + r32g);
            CP_COMMIT();
        }

        int k0 = kt << 6;
        uint32_t stg = sbase + (uint32_t)(kt & 1) * AT_STG_BY;
        uint32_t ks_b = stg;
        uint32_t vs_b = stg + 64 * AT_S * 2;

        // ---- S = Q K^T ----
        float sc[8][4];
        #pragma unroll
        for (int nt = 0; nt < 8; nt++)
            #pragma unroll
            for (int i = 0; i < 4; i++) sc[nt][i] = 0.f;
        #pragma unroll
        for (int kc = 0; kc < 4; kc++) {
            int kk = kc * 16;
            #pragma unroll
            for (int np = 0; np < 4; np++) {
                uint32_t r0, r1, r2, r3;
                LDSM4(r0, r1, r2, r3,
                      ks_b + kb_off + (uint32_t)((np * 16 * AT_S + kk) * 2));
                uint32_t b0[2] = {r0, r1}, b1[2] = {r2, r3};
                mma16(sc[2 * np],     qa[kc], b0);
                mma16(sc[2 * np + 1], qa[kc], b1);
            }
        }

        // ---- scale + causal mask + row max ----
        float mx0 = -1e30f, mx1 = -1e30f;
        #pragma unroll
        for (int nt = 0; nt < 8; nt++) {
            int c0 = k0 + nt * 8 + 2 * r;
            int c1 = c0 + 1;
            sc[nt][0] = (c0 <= row0) ? sc[nt][0] * 0.03125f : -1e30f;
            sc[nt][1] = (c1 <= row0) ? sc[nt][1] * 0.03125f : -1e30f;
            sc[nt][2] = (c0 <= row1) ? sc[nt][2] * 0.03125f : -1e30f;
            sc[nt][3] = (c1 <= row1) ? sc[nt][3] * 0.03125f : -1e30f;
            mx0 = fmaxf(mx0, fmaxf(sc[nt][0], sc[nt][1]));
            mx1 = fmaxf(mx1, fmaxf(sc[nt][2], sc[nt][3]));
        }
        mx0 = fmaxf(mx0, __shfl_xor_sync(0xffffffffu, mx0, 1));
        mx0 = fmaxf(mx0, __shfl_xor_sync(0xffffffffu, mx0, 2));
        mx1 = fmaxf(mx1, __shfl_xor_sync(0xffffffffu, mx1, 1));
        mx1 = fmaxf(mx1, __shfl_xor_sync(0xffffffffu, mx1, 2));

        float mn0 = fmaxf(mi0, mx0), mn1 = fmaxf(mi1, mx1);
        float corr0 = __expf(mi0 - mn0);
        float corr1 = __expf(mi1 - mn1);

        // ---- exp; P packed in registers ----
        uint32_t hp0[8], hp1[8];
        float s0 = 0.f, s1 = 0.f;
        #pragma unroll
        for (int nt = 0; nt < 8; nt++) {
            float2 f01, f23;
            hp0[nt] = exp2h2((sc[nt][0] - mn0) * LOG2E,
                             (sc[nt][1] - mn0) * LOG2E, &f01);
            hp1[nt] = exp2h2((sc[nt][2] - mn1) * LOG2E,
                             (sc[nt][3] - mn1) * LOG2E, &f23);
            s0 += f01.x + f01.y;
            s1 += f23.x + f23.y;
        }
        s0 += __shfl_xor_sync(0xffffffffu, s0, 1);
        s0 += __shfl_xor_sync(0xffffffffu, s0, 2);
        s1 += __shfl_xor_sync(0xffffffffu, s1, 1);
        s1 += __shfl_xor_sync(0xffffffffu, s1, 2);
        li0 = li0 * corr0 + s0;
        li1 = li1 * corr1 + s1;
        mi0 = mn0; mi1 = mn1;

        #pragma unroll
        for (int nt = 0; nt < 8; nt++) {
            oa[nt][0] *= corr0; oa[nt][1] *= corr0;
            oa[nt][2] *= corr1; oa[nt][3] *= corr1;
        }

        // ---- O += P V ----
        #pragma unroll
        for (int scx = 0; scx < 4; scx++) {
            int s8 = scx * 16;
            uint32_t pa[4] = {hp0[2 * scx], hp1[2 * scx],
                              hp0[2 * scx + 1], hp1[2 * scx + 1]};
            #pragma unroll
            for (int np = 0; np < 4; np++) {
                uint32_t r0, r1, r2, r3;
                LDSM4T(r0, r1, r2, r3,
                       vs_b + vb_off + (uint32_t)((s8 * AT_S + np * 16) * 2));
                uint32_t b0[2] = {r0, r1}, b1[2] = {r2, r3};
                mma16(oa[2 * np],     pa, b0);
                mma16(oa[2 * np + 1], pa, b1);
            }
        }
    }

    float inv0 = 1.f / li0, inv1 = 1.f / li1;
    __half* Ob = O + (size_t)b * T_ * C_ + h * 64;
    #pragma unroll
    for (int nt = 0; nt < 8; nt++) {
        int cc = nt * 8 + 2 * r;
        *(__half2*)&Ob[(size_t)row0 * C_ + cc] =
            __floats2half2_rn(oa[nt][0] * inv0, oa[nt][1] * inv0);
        *(__half2*)&Ob[(size_t)row1 * C_ + cc] =
            __floats2half2_rn(oa[nt][2] * inv1, oa[nt][3] * inv1);
    }
}

// ---------------- launcher -------------------------------------------------
extern "C" void kernel_launch(void* const* d_in, const int* in_sizes, int n_in,
                              void* d_out, int out_size) {
    const float* x     = (const float*)d_in[0];
    const float* Wq    = (const float*)d_in[1];
    const float* Wk    = (const float*)d_in[2];
    const float* Wv    = (const float*)d_in[3];
    const float* Wproj = (const float*)d_in[4];
    const float* bproj = (const float*)d_in[5];
    const float* W1    = (const float*)d_in[6];
    const float* b1    = (const float*)d_in[7];
    const float* W2    = (const float*)d_in[8];
    const float* b2    = (const float*)d_in[9];
    const float* ln1s  = (const float*)d_in[10];
    const float* ln1b  = (const float*)d_in[11];
    const float* ln2s  = (const float*)d_in[12];
    const float* ln2b  = (const float*)d_in[13];
    float* out = (float*)d_out;

    __half *h, *wqkv, *wp, *w1, *w2, *qkv, *attn, *h2, *f1;
    float *x1;
    cudaGetSymbolAddress((void**)&h,    g_h);
    cudaGetSymbolAddress((void**)&wqkv, g_wqkv);
    cudaGetSymbolAddress((void**)&wp,   g_wp);
    cudaGetSymbolAddress((void**)&w1,   g_w1);
    cudaGetSymbolAddress((void**)&w2,   g_w2);
    cudaGetSymbolAddress((void**)&qkv,  g_qkv);
    cudaGetSymbolAddress((void**)&attn, g_attn);
    cudaGetSymbolAddress((void**)&x1,   g_x1);
    cudaGetSymbolAddress((void**)&h2,   g_h2);
    cudaGetSymbolAddress((void**)&f1,   g_f1);

    cudaFuncSetAttribute(attn_h,
                         cudaFuncAttributeMaxDynamicSharedMemorySize, ATT_SMEM_BYTES);
    cudaFuncSetAttribute(hgemm<0, 0>,
                         cudaFuncAttributeMaxDynamicSharedMemorySize, H_SMEM);
    cudaFuncSetAttribute(hgemm<0, 1>,
                         cudaFuncAttributeMaxDynamicSharedMemorySize, H_SMEM);
    cudaFuncSetAttribute(hgemm<1, 1>,
                         cudaFuncAttributeMaxDynamicSharedMemorySize, H_SMEM);

    // LN1 + merged weight prep
    ln_kernel<<<BT, 256>>>(x, ln1s, ln1b, h);
    prep_w<<<12288, dim3(32, 8)>>>(Wq, Wk, Wv, Wproj, W1, W2, wqkv, wp, w1, w2);

    // fused QKV projection (fp16 out)
    hgemm<0, 1><<<dim3(C3 / 128, BT / 128), 256, H_SMEM>>>(
        h, wqkv, nullptr, nullptr, qkv, BT, C3, C_);

    // attention
    attn_h<<<dim3(T_ / 128, B_ * H_), 256, ATT_SMEM_BYTES>>>(qkv, attn);

    // out proj + residual (fp32 out)
    dim3 g1(C_ / 128, BT / 128);
    hgemm<0, 0><<<g1, 256, H_SMEM>>>(attn, wp, bproj, x, x1, BT, C_, C_);

    // LN2 (fp16 out)
    ln_kernel<<<BT, 256>>>(x1, ln2s, ln2b, h2);

    // MLP
    hgemm<1, 1><<<dim3(FF / 128, BT / 128), 256, H_SMEM>>>(
        h2, w1, b1, nullptr, f1, BT, FF, C_);
    hgemm<0, 0><<<g1, 256, H_SMEM>>>(f1, w2, b2, x1, out, BT, C_, FF);
}

// round 13
// speedup vs baseline: 1.0752x; 1.0147x over previous
#include <cuda_runtime.h>
#include <cuda_fp16.h>
#include <cstdint>

// Problem constants
#define B_ 2
#define T_ 2048
#define C_ 1024
#define H_ 16
#define D_ 64
#define BT 4096          // B_*T_
#define FF 4096          // 4*C_
#define C3 3072          // 3*C_

// ---------------- scratch (static device globals) --------------------------
__device__ __half g_h   [BT * C_];   // LN1 output (fp16)
__device__ __half g_wqkv[C3 * C_];   // QKV weights [N=3C, K=C] fp16
__device__ __half g_wp  [C_ * C_];   // Wproj^T [N,K] fp16
__device__ __half g_w1  [FF * C_];   // W1^T [N=FF, K=C] fp16
__device__ __half g_w2  [C_ * FF];   // W2^T [N=C, K=FF] fp16
__device__ __half g_qkv [BT * C3];   // fused q|k|v [B,T,3C] fp16
__device__ __half g_attn[BT * C_];   // concat heads fp16
__device__ float  g_x1  [BT * C_];   // x + attn@Wproj + bproj (fp32)
__device__ __half g_h2  [BT * C_];   // LN2 output fp16
__device__ __half g_f1  [BT * FF];   // relu(h2@W1+b1) fp16

// ---------------- helpers --------------------------------------------------
__device__ __forceinline__ void mma16(float* c, const uint32_t* a, const uint32_t* b) {
    asm volatile(
        "mma.sync.aligned.m16n8k16.row.col.f32.f16.f16.f32 "
        "{%0,%1,%2,%3}, {%4,%5,%6,%7}, {%8,%9}, {%0,%1,%2,%3};"
        : "+f"(c[0]), "+f"(c[1]), "+f"(c[2]), "+f"(c[3])
        : "r"(a[0]), "r"(a[1]), "r"(a[2]), "r"(a[3]), "r"(b[0]), "r"(b[1]));
}
#define LDSM4(R0, R1, R2, R3, addr) \
    asm volatile("ldmatrix.sync.aligned.m8n8.x4.shared.b16 {%0,%1,%2,%3}, [%4];" \
                 : "=r"(R0), "=r"(R1), "=r"(R2), "=r"(R3) : "r"(addr))
#define LDSM4T(R0, R1, R2, R3, addr) \
    asm volatile("ldmatrix.sync.aligned.m8n8.x4.trans.shared.b16 {%0,%1,%2,%3}, [%4];" \
                 : "=r"(R0), "=r"(R1), "=r"(R2), "=r"(R3) : "r"(addr))

__device__ __forceinline__ uint32_t exp2h2(float t0, float t1, float2* f) {
    __half2 hh = __floats2half2_rn(t0, t1);
    uint32_t hin = *reinterpret_cast<uint32_t*>(&hh);
    uint32_t hout;
    asm("ex2.approx.f16x2 %0, %1;" : "=r"(hout) : "r"(hin));
    __half2 he = *reinterpret_cast<__half2*>(&hout);
    *f = __half22float2(he);
    return hout;
}
__device__ __forceinline__ uint32_t smem_u32(const void* p) {
    uint32_t a;
    asm("{ .reg .u64 t; cvta.to.shared.u64 t, %1; cvt.u32.u64 %0, t; }"
        : "=r"(a) : "l"(p));
    return a;
}
#define CP16(dst, src) \
    asm volatile("cp.async.cg.shared.global [%0], [%1], 16;" \
                 :: "r"(dst), "l"(src) : "memory")
#define CP_COMMIT() asm volatile("cp.async.commit_group;" ::: "memory")
#define CP_WAIT0()  asm volatile("cp.async.wait_group 0;"  ::: "memory")
#define CP_WAIT1()  asm volatile("cp.async.wait_group 1;"  ::: "memory")

// ---------------- LayerNorm (fp32 in, fp16 out) ---------------------------
__global__ void ln_kernel(const float* __restrict__ x,
                          const float* __restrict__ sc,
                          const float* __restrict__ bi,
                          __half* __restrict__ out) {
    int row = blockIdx.x;
    const float* xr = x + (size_t)row * C_;
    __half* orow = out + (size_t)row * C_;
    int tid = threadIdx.x;

    float4 v = ((const float4*)xr)[tid];
    float s  = v.x + v.y + v.z + v.w;
    float ss = v.x*v.x + v.y*v.y + v.z*v.z + v.w*v.w;
    #pragma unroll
    for (int o = 16; o; o >>= 1) {
        s  += __shfl_xor_sync(0xffffffffu, s,  o);
        ss += __shfl_xor_sync(0xffffffffu, ss, o);
    }
    __shared__ float sm[8], sm2[8];
    if ((tid & 31) == 0) { sm[tid >> 5] = s; sm2[tid >> 5] = ss; }
    __syncthreads();
    if (tid < 32) {
        float a  = (tid < 8) ? sm[tid]  : 0.f;
        float b2 = (tid < 8) ? sm2[tid] : 0.f;
        #pragma unroll
        for (int o = 4; o; o >>= 1) {
            a  += __shfl_xor_sync(0xffffffffu, a,  o);
            b2 += __shfl_xor_sync(0xffffffffu, b2, o);
        }
        if (tid == 0) { sm[0] = a; sm2[0] = b2; }
    }
    __syncthreads();
    float mean = sm[0] * (1.f / C_);
    float var  = sm2[0] * (1.f / C_) - mean * mean;
    float rstd = rsqrtf(var + 1e-6f);

    float4 sv = ((const float4*)sc)[tid];
    float4 bv = ((const float4*)bi)[tid];
    __half2 h0 = __floats2half2_rn((v.x - mean) * rstd * sv.x + bv.x,
                                   (v.y - mean) * rstd * sv.y + bv.y);
    __half2 h1 = __floats2half2_rn((v.z - mean) * rstd * sv.z + bv.z,
                                   (v.w - mean) * rstd * sv.w + bv.w);
    uint2 o8;
    o8.x = *reinterpret_cast<uint32_t*>(&h0);
    o8.y = *reinterpret_cast<uint32_t*>(&h1);
    *(uint2*)&orow[tid * 4] = o8;
}

// ---------------- merged weight prep -------------------------------------
__global__ void prep_w(const float* __restrict__ Wq, const float* __restrict__ Wk,
                       const float* __restrict__ Wv, const float* __restrict__ Wproj,
                       const float* __restrict__ W1, const float* __restrict__ W2,
                       __half* __restrict__ wqkv, __half* __restrict__ wp,
                       __half* __restrict__ w1, __half* __restrict__ w2) {
    __shared__ float t[32][33];
    int tIdx = blockIdx.x;
    const float* src; __half* dst;
    int R, Cc, bx, by;
    if (tIdx < 3072) {
        int w = tIdx >> 10, rem = tIdx & 1023;
        int head = rem >> 6, q = rem & 63;
        bx = q & 1; by = q >> 1;
        const float* Wsrc = (w == 0) ? Wq : (w == 1) ? Wk : Wv;
        src = Wsrc + (size_t)head * C_ * 64;
        dst = wqkv + (size_t)w * C_ * C_ + (size_t)head * 64 * C_;
        R = C_; Cc = 64;
    } else if (tIdx < 4096) {
        int rem = tIdx - 3072;
        bx = rem & 31; by = rem >> 5;
        src = Wproj; dst = wp; R = C_; Cc = C_;
    } else if (tIdx < 8192) {
        int rem = tIdx - 4096;
        bx = rem & 127; by = rem >> 7;
        src = W1; dst = w1; R = C_; Cc = FF;
    } else {
        int rem = tIdx - 8192;
        bx = rem & 31; by = rem >> 5;
        src = W2; dst = w2; R = FF; Cc = C_;
    }
    int r0 = by * 32, c0 = bx * 32;
    int x = threadIdx.x, y = threadIdx.y;
    #pragma unroll
    for (int i = 0; i < 32; i += 8)
        t[y + i][x] = src[(size_t)(r0 + y + i) * Cc + c0 + x];
    __syncthreads();
    #pragma unroll
    for (int i = 0; i < 32; i += 8)
        dst[(size_t)(c0 + y + i) * R + r0 + x] = __float2half(t[x][y + i]);
}

// ---------------- fp16 GEMM (BK=64, 3-stage cp.async, ldmatrix) ------------
// R10/R12-validated ordering: compute first, prefetch after, commit at end.
#define H_SA 72                       // halves stride (144 B)
#define H_STG_H (128 * H_SA * 2)      // A+B halves per stage
#define H_BOFF  (128 * H_SA)
#define H_STG_BY (H_STG_H * 2)        // 36864 bytes
#define H_SMEM  (3 * H_STG_BY)        // 110592 bytes

template <int RELU, int HOUT>
__global__ void __launch_bounds__(256, 2) hgemm(
    const __half* __restrict__ A, const __half* __restrict__ Bw,
    const float* __restrict__ bias, const float* __restrict__ resid,
    void* __restrict__ Cout, int M, int N, int K)
{
    extern __shared__ __half smh[];
    uint32_t sbase = smem_u32(smh);

    int tid  = threadIdx.x;
    int wid  = tid >> 5, lane = tid & 31;
    int g    = lane >> 2, r = lane & 3;
    int bm   = blockIdx.y, bn = blockIdx.x;
    int wm   = (wid & 1) * 64;
    int wn   = (wid >> 1) * 32;

    const __half* Ab = A  + (size_t)bm * 128 * K;
    const __half* Bb = Bw + (size_t)bn * 128 * K;

    int lr = tid >> 3, seg = tid & 7;
    const __half* Asrc = Ab + (size_t)lr * K + seg * 8;
    const __half* Bsrc = Bb + (size_t)lr * K + seg * 8;
    uint32_t ad = sbase + (uint32_t)(lr * 144 + seg * 16);
    uint32_t bd = ad + H_BOFF * 2;
    const size_t r32 = (size_t)32 * K;

    uint32_t aoff = (uint32_t)(((lane & 7) + ((lane >> 3) & 1) * 8) * H_SA
                               + (lane >> 4) * 8) * 2;
    uint32_t boff = (uint32_t)(((lane & 7) + ((lane >> 4) & 1) * 8) * H_SA
                               + ((lane >> 3) & 1) * 8) * 2;

    float c[4][4][4];
    #pragma unroll
    for (int mt = 0; mt < 4; mt++)
        #pragma unroll
        for (int nt = 0; nt < 4; nt++)
            #pragma unroll
            for (int i = 0; i < 4; i++) c[mt][nt][i] = 0.f;

    int nch = K >> 6;

    // prologue: 2 stages in flight
    #pragma unroll
    for (int pc = 0; pc < 2; pc++) {
        uint32_t so = (uint32_t)pc * H_STG_BY;
        int kt = pc << 6;
        #pragma unroll
        for (int p = 0; p < 4; p++) {
            CP16(ad + so + (uint32_t)p * 32 * 144, Asrc + p * r32 + kt);
            CP16(bd + so + (uint32_t)p * 32 * 144, Bsrc + p * r32 + kt);
        }
        CP_COMMIT();
    }

    for (int ch = 0; ch < nch; ch++) {
        int st = ch % 3;
        CP_WAIT1();
        __syncthreads();

        uint32_t abase = sbase + (uint32_t)st * H_STG_BY + aoff;
        uint32_t bbase = sbase + (uint32_t)st * H_STG_BY + H_BOFF * 2 + boff;
        #pragma unroll
        for (int ks = 0; ks < 4; ks++) {
            int kk = ks * 16;
            uint32_t af[4][4], bf[4][2];
            #pragma unroll
            for (int mt = 0; mt < 4; mt++)
                LDSM4(af[mt][0], af[mt][1], af[mt][2], af[mt][3],
                      abase + (uint32_t)(((wm + mt * 16) * H_SA + kk) * 2));
            #pragma unroll
            for (int np = 0; np < 2; np++) {
                uint32_t r0, r1, r2, r3;
                LDSM4(r0, r1, r2, r3,
                      bbase + (uint32_t)(((wn + np * 16) * H_SA + kk) * 2));
                bf[2 * np][0] = r0; bf[2 * np][1] = r1;
                bf[2 * np + 1][0] = r2; bf[2 * np + 1][1] = r3;
            }
            #pragma unroll
            for (int mt = 0; mt < 4; mt++)
                #pragma unroll
                for (int nt = 0; nt < 4; nt++)
                    mma16(c[mt][nt], af[mt], bf[nt]);
        }

        int nc2 = ch + 2;
        if (nc2 < nch) {
            int kt = nc2 << 6;
            uint32_t so = (uint32_t)(nc2 % 3) * H_STG_BY;
            #pragma unroll
            for (int p = 0; p < 4; p++) {
                CP16(ad + so + (uint32_t)p * 32 * 144, Asrc + p * r32 + kt);
                CP16(bd + so + (uint32_t)p * 32 * 144, Bsrc + p * r32 + kt);
            }
        }
        CP_COMMIT();
    }

    #pragma unroll
    for (int mt = 0; mt < 4; mt++) {
        #pragma unroll
        for (int rr = 0; rr < 2; rr++) {
            int m = bm * 128 + wm + mt * 16 + g + rr * 8;
            const float* Rrow = resid ? resid + (size_t)m * N + bn * 128 : nullptr;
            #pragma unroll
            for (int nt = 0; nt < 4; nt++) {
                int nc = wn + nt * 8 + 2 * r;
                float v0 = c[mt][nt][rr * 2 + 0];
                float v1 = c[mt][nt][rr * 2 + 1];
                if (bias)  { v0 += bias[bn * 128 + nc]; v1 += bias[bn * 128 + nc + 1]; }
                if (resid) { v0 += Rrow[nc]; v1 += Rrow[nc + 1]; }
                if (RELU)  { v0 = fmaxf(v0, 0.f); v1 = fmaxf(v1, 0.f); }
                if (HOUT) {
                    __half* Crow = (__half*)Cout + (size_t)m * N + bn * 128;
                    *(__half2*)&Crow[nc] = __floats2half2_rn(v0, v1);
                } else {
                    float* Crow = (float*)Cout + (size_t)m * N + bn * 128;
                    *(float2*)&Crow[nc] = make_float2(v0, v1);
                }
            }
        }
    }
}

// ---------------- fp16 flash attention: mask-free fast path ----------------
// Causal mask is warp-uniform-skippable: tile kt needs masking iff
// k0+63 > q0+m0 (min row in warp). Unmasked tiles use the identical
// S*0.03125f arithmetic -> bit-identical results, ~64 fewer alu ops/tile.
#define AT_S 72
#define AT_STG_H (2 * 64 * AT_S)                 // K+V halves per stage
#define AT_STG_BY (AT_STG_H * 2)                 // 18432 bytes
#define ATT_SMEM_BYTES (2 * AT_STG_BY)           // 36864 bytes (2 stages)
#define LOG2E 1.4426950408889634f

__global__ void __launch_bounds__(256, 2) attn_h(
    const __half* __restrict__ QKV, __half* __restrict__ O)
{
    extern __shared__ __half sma[];
    uint32_t sbase = smem_u32(sma);

    int tid = threadIdx.x;
    int wid = tid >> 5, lane = tid & 31;
    int g = lane >> 2, r = lane & 3;
    int b = blockIdx.y >> 4, h = blockIdx.y & 15;
    // reversed order: heaviest (largest q0) CTAs launch first
    int q0 = (gridDim.x - 1 - blockIdx.x) * 128;
    int m0 = wid * 16;

    const __half* Qb = QKV + (size_t)b * T_ * C3 + h * 64;
    const __half* Kb = Qb + C_;
    const __half* Vb = Qb + 2 * C_;

    int row0 = q0 + m0 + g;
    int row1 = row0 + 8;

    uint32_t kb_off = (uint32_t)(((lane & 7) + ((lane >> 4) & 1) * 8) * AT_S
                                 + ((lane >> 3) & 1) * 8) * 2;
    uint32_t vb_off = (uint32_t)(((lane & 7) + ((lane >> 3) & 1) * 8) * AT_S
                                 + (lane >> 4) * 8) * 2;

    int lr = tid >> 3, seg = tid & 7;
    const __half* Ksrc = Kb + (size_t)lr * C3 + seg * 8;
    const __half* Vsrc = Vb + (size_t)lr * C3 + seg * 8;
    uint32_t kd = sbase + (uint32_t)(lr * AT_S + seg * 8) * 2;
    uint32_t vd = kd + 64 * AT_S * 2;
    const size_t r32g = (size_t)32 * C3;

    uint32_t qa[4][4];
    #pragma unroll
    for (int kc = 0; kc < 4; kc++) {
        int d0 = kc * 16;
        qa[kc][0] = *(const uint32_t*)&Qb[(size_t)row0 * C3 + d0 + 2 * r    ];
        qa[kc][1] = *(const uint32_t*)&Qb[(size_t)row1 * C3 + d0 + 2 * r    ];
        qa[kc][2] = *(const uint32_t*)&Qb[(size_t)row0 * C3 + d0 + 2 * r + 8];
        qa[kc][3] = *(const uint32_t*)&Qb[(size_t)row1 * C3 + d0 + 2 * r + 8];
    }

    float oa[8][4];
    #pragma unroll
    for (int nt = 0; nt < 8; nt++)
        #pragma unroll
        for (int i = 0; i < 4; i++) oa[nt][i] = 0.f;
    float mi0 = -1e30f, mi1 = -1e30f, li0 = 0.f, li1 = 0.f;

    int ntiles = (q0 >> 6) + 2;

    // prologue: load tile 0 into stage 0
    {
        CP16(kd, Ksrc);                      CP16(kd + 32 * AT_S * 2, Ksrc + r32g);
        CP16(vd, Vsrc);                      CP16(vd + 32 * AT_S * 2, Vsrc + r32g);
        CP_COMMIT();
    }

    for (int kt = 0; kt < ntiles; kt++) {
        CP_WAIT0();
        __syncthreads();

        // prefetch next tile into the other stage (overlaps compute below)
        if (kt + 1 < ntiles) {
            int kn = (kt + 1) << 6;
            uint32_t so = (uint32_t)((kt + 1) & 1) * AT_STG_BY;
            const __half* Ks2 = Ksrc + (size_t)kn * C3;
            const __half* Vs2 = Vsrc + (size_t)kn * C3;
            CP16(kd + so, Ks2);              CP16(kd + so + 32 * AT_S * 2, Ks2 + r32g);
            CP16(vd + so, Vs2);              CP16(vd + so + 32 * AT_S * 2, Vs2 + r32g);
            CP_COMMIT();
        }

        int k0 = kt << 6;
        uint32_t stg = sbase + (uint32_t)(kt & 1) * AT_STG_BY;
        uint32_t ks_b = stg;
        uint32_t vs_b = stg + 64 * AT_S * 2;

        // ---- S = Q K^T ----
        float sc[8][4];
        #pragma unroll
        for (int nt = 0; nt < 8; nt++)
            #pragma unroll
            for (int i = 0; i < 4; i++) sc[nt][i] = 0.f;
        #pragma unroll
        for (int kc = 0; kc < 4; kc++) {
            int kk = kc * 16;
            #pragma unroll
            for (int np = 0; np < 4; np++) {
                uint32_t r0, r1, r2, r3;
                LDSM4(r0, r1, r2, r3,
                      ks_b + kb_off + (uint32_t)((np * 16 * AT_S + kk) * 2));
                uint32_t b0[2] = {r0, r1}, b1[2] = {r2, r3};
                mma16(sc[2 * np],     qa[kc], b0);
                mma16(sc[2 * np + 1], qa[kc], b1);
            }
        }

        // ---- scale (+causal mask only when warp-uniformly needed) + max ----
        float mx0 = -1e30f, mx1 = -1e30f;
        if (k0 + 63 > q0 + m0) {
            #pragma unroll
            for (int nt = 0; nt < 8; nt++) {
                int c0 = k0 + nt * 8 + 2 * r;
                int c1 = c0 + 1;
                sc[nt][0] = (c0 <= row0) ? sc[nt][0] * 0.03125f : -1e30f;
                sc[nt][1] = (c1 <= row0) ? sc[nt][1] * 0.03125f : -1e30f;
                sc[nt][2] = (c0 <= row1) ? sc[nt][2] * 0.03125f : -1e30f;
                sc[nt][3] = (c1 <= row1) ? sc[nt][3] * 0.03125f : -1e30f;
                mx0 = fmaxf(mx0, fmaxf(sc[nt][0], sc[nt][1]));
                mx1 = fmaxf(mx1, fmaxf(sc[nt][2], sc[nt][3]));
            }
        } else {
            #pragma unroll
            for (int nt = 0; nt < 8; nt++) {
                sc[nt][0] *= 0.03125f;
                sc[nt][1] *= 0.03125f;
                sc[nt][2] *= 0.03125f;
                sc[nt][3] *= 0.03125f;
                mx0 = fmaxf(mx0, fmaxf(sc[nt][0], sc[nt][1]));
                mx1 = fmaxf(mx1, fmaxf(sc[nt][2], sc[nt][3]));
            }
        }
        mx0 = fmaxf(mx0, __shfl_xor_sync(0xffffffffu, mx0, 1));
        mx0 = fmaxf(mx0, __shfl_xor_sync(0xffffffffu, mx0, 2));
        mx1 = fmaxf(mx1, __shfl_xor_sync(0xffffffffu, mx1, 1));
        mx1 = fmaxf(mx1, __shfl_xor_sync(0xffffffffu, mx1, 2));

        float mn0 = fmaxf(mi0, mx0), mn1 = fmaxf(mi1, mx1);
        float corr0 = __expf(mi0 - mn0);
        float corr1 = __expf(mi1 - mn1);

        // ---- exp; P packed in registers ----
        uint32_t hp0[8], hp1[8];
        float s0 = 0.f, s1 = 0.f;
        #pragma unroll
        for (int nt = 0; nt < 8; nt++) {
            float2 f01, f23;
            hp0[nt] = exp2h2((sc[nt][0] - mn0) * LOG2E,
                             (sc[nt][1] - mn0) * LOG2E, &f01);
            hp1[nt] = exp2h2((sc[nt][2] - mn1) * LOG2E,
                             (sc[nt][3] - mn1) * LOG2E, &f23);
            s0 += f01.x + f01.y;
            s1 += f23.x + f23.y;
        }
        s0 += __shfl_xor_sync(0xffffffffu, s0, 1);
        s0 += __shfl_xor_sync(0xffffffffu, s0, 2);
        s1 += __shfl_xor_sync(0xffffffffu, s1, 1);
        s1 += __shfl_xor_sync(0xffffffffu, s1, 2);
        li0 = li0 * corr0 + s0;
        li1 = li1 * corr1 + s1;
        mi0 = mn0; mi1 = mn1;

        #pragma unroll
        for (int nt = 0; nt < 8; nt++) {
            oa[nt][0] *= corr0; oa[nt][1] *= corr0;
            oa[nt][2] *= corr1; oa[nt][3] *= corr1;
        }

        // ---- O += P V ----
        #pragma unroll
        for (int scx = 0; scx < 4; scx++) {
            int s8 = scx * 16;
            uint32_t pa[4] = {hp0[2 * scx], hp1[2 * scx],
                              hp0[2 * scx + 1], hp1[2 * scx + 1]};
            #pragma unroll
            for (int np = 0; np < 4; np++) {
                uint32_t r0, r1, r2, r3;
                LDSM4T(r0, r1, r2, r3,
                       vs_b + vb_off + (uint32_t)((s8 * AT_S + np * 16) * 2));
                uint32_t b0[2] = {r0, r1}, b1[2] = {r2, r3};
                mma16(oa[2 * np],     pa, b0);
                mma16(oa[2 * np + 1], pa, b1);
            }
        }
    }

    float inv0 = 1.f / li0, inv1 = 1.f / li1;
    __half* Ob = O + (size_t)b * T_ * C_ + h * 64;
    #pragma unroll
    for (int nt = 0; nt < 8; nt++) {
        int cc = nt * 8 + 2 * r;
        *(__half2*)&Ob[(size_t)row0 * C_ + cc] =
            __floats2half2_rn(oa[nt][0] * inv0, oa[nt][1] * inv0);
        *(__half2*)&Ob[(size_t)row1 * C_ + cc] =
            __floats2half2_rn(oa[nt][2] * inv1, oa[nt][3] * inv1);
    }
}

// ---------------- launcher -------------------------------------------------
extern "C" void kernel_launch(void* const* d_in, const int* in_sizes, int n_in,
                              void* d_out, int out_size) {
    const float* x     = (const float*)d_in[0];
    const float* Wq    = (const float*)d_in[1];
    const float* Wk    = (const float*)d_in[2];
    const float* Wv    = (const float*)d_in[3];
    const float* Wproj = (const float*)d_in[4];
    const float* bproj = (const float*)d_in[5];
    const float* W1    = (const float*)d_in[6];
    const float* b1    = (const float*)d_in[7];
    const float* W2    = (const float*)d_in[8];
    const float* b2    = (const float*)d_in[9];
    const float* ln1s  = (const float*)d_in[10];
    const float* ln1b  = (const float*)d_in[11];
    const float* ln2s  = (const float*)d_in[12];
    const float* ln2b  = (const float*)d_in[13];
    float* out = (float*)d_out;

    __half *h, *wqkv, *wp, *w1, *w2, *qkv, *attn, *h2, *f1;
    float *x1;
    cudaGetSymbolAddress((void**)&h,    g_h);
    cudaGetSymbolAddress((void**)&wqkv, g_wqkv);
    cudaGetSymbolAddress((void**)&wp,   g_wp);
    cudaGetSymbolAddress((void**)&w1,   g_w1);
    cudaGetSymbolAddress((void**)&w2,   g_w2);
    cudaGetSymbolAddress((void**)&qkv,  g_qkv);
    cudaGetSymbolAddress((void**)&attn, g_attn);
    cudaGetSymbolAddress((void**)&x1,   g_x1);
    cudaGetSymbolAddress((void**)&h2,   g_h2);
    cudaGetSymbolAddress((void**)&f1,   g_f1);

    cudaFuncSetAttribute(attn_h,
                         cudaFuncAttributeMaxDynamicSharedMemorySize, ATT_SMEM_BYTES);
    cudaFuncSetAttribute(hgemm<0, 0>,
                         cudaFuncAttributeMaxDynamicSharedMemorySize, H_SMEM);
    cudaFuncSetAttribute(hgemm<0, 1>,
                         cudaFuncAttributeMaxDynamicSharedMemorySize, H_SMEM);
    cudaFuncSetAttribute(hgemm<1, 1>,
                         cudaFuncAttributeMaxDynamicSharedMemorySize, H_SMEM);

    // LN1 + merged weight prep
    ln_kernel<<<BT, 256>>>(x, ln1s, ln1b, h);
    prep_w<<<12288, dim3(32, 8)>>>(Wq, Wk, Wv, Wproj, W1, W2, wqkv, wp, w1, w2);

    // fused QKV projection (fp16 out)
    hgemm<0, 1><<<dim3(C3 / 128, BT / 128), 256, H_SMEM>>>(
        h, wqkv, nullptr, nullptr, qkv, BT, C3, C_);

    // attention
    attn_h<<<dim3(T_ / 128, B_ * H_), 256, ATT_SMEM_BYTES>>>(qkv, attn);

    // out proj + residual (fp32 out)
    dim3 g1(C_ / 128, BT / 128);
    hgemm<0, 0><<<g1, 256, H_SMEM>>>(attn, wp, bproj, x, x1, BT, C_, C_);

    // LN2 (fp16 out)
    ln_kernel<<<BT, 256>>>(x1, ln2s, ln2b, h2);

    // MLP
    hgemm<1, 1><<<dim3(FF / 128, BT / 128), 256, H_SMEM>>>(
        h2, w1, b1, nullptr, f1, BT, FF, C_);
    hgemm<0, 0><<<g1, 256, H_SMEM>>>(f1, w2, b2, x1, out, BT, C_, FF);
}